// round 10
// baseline (speedup 1.0000x reference)
#include <cuda_runtime.h>
#include <cstdint>

// HistogramLayer inference:
//   hist_probs[b,d] = freq[b,d] / sum_b freq[b,d]
//   bin[r,d] = clip(searchsorted_right(edges[:,d], x[r,d]) - 1, 0, 7)
//   out[r] = prod_d hist_probs[bin[r,d], d]
//
// Edges are base[b]*scale[d], base = integers -4..4; edges[8][d] = 4*scale
// exactly, so edge[b][d] = round_rn(((b-4)/4) * e8): ONE fp32 rounding
// reproduced with __fmul_rn in the slow path (explicit intrinsics prevent FMA
// contraction -- load-bearing, see R3 rel_err incident).
//
// NEW (R9): warp-voted verification skip. The guess t = fma(x, ~1/scale, 4)
// has total error < ~3e-6 vs the exact boundary positions (fdividef 2ulp +
// fma rounding + edge-rounding shift, all mapped into t-units). If t is
// farther than EPS = 8e-6 from every integer, floor(t) is PROVABLY the
// reference bin -- no edge reconstruction needed. One warp vote over all
// 16 features x 32 lanes selects the fast path (~99% of warp-rows).
// Slow path = R8's bit-exact find_bin, unchanged (rel_err 3.8e-7 empirically).

#define HD  16
#define HNB 8
#define MAGICF 12582912.0f   // 1.5 * 2^23
#define MAGICI 0x4B400000
#define EPSQ   8e-6f

__device__ __forceinline__ int find_bin_slow(float xv, float inv, float e8)
{
    const float t  = fmaf(xv, inv, 4.0f);
    const float tf = floorf(t);
    int b = (int)tf;
    const float u   = fmaf(tf, 0.25f, -1.0f);        // (b-4)/4, exact
    const float uhi = fmaf(tf, 0.25f, -0.75f);       // (b-3)/4, exact
    const float elo = __fmul_rn(u,   e8);            // == reference edge[b]
    const float ehi = __fmul_rn(uhi, e8);            // == reference edge[b+1]
    const int shi = (int)(__float_as_uint(__fadd_rn(xv, -ehi)) >> 31);
    const int slo = (int)(__float_as_uint(__fadd_rn(xv, -elo)) >> 31);
    b += 1 - shi - slo;
    return max(0, min(HNB - 1, b));
}

// Fast guess: rn via magic add, floor-fix from exact sign of (t - rn(t)).
// Also accumulates min-distance-to-integer into m.
__device__ __forceinline__ int fast_bin(float xv, float inv, float& m)
{
    const float t = fmaf(xv, inv, 4.0f);
    const float r = __fadd_rn(t, MAGICF);
    const float f = __fadd_rn(r, -MAGICF);           // rn(t), exact
    const float d = __fadd_rn(t, -f);                // exact (Sterbenz)
    m = fminf(m, fabsf(d));
    int b = (int)__float_as_uint(r) - MAGICI;        // rn(t) as int
    b -= (int)(__float_as_uint(d) >> 31);            // floor fix (d<0 -> -1)
    return max(0, min(HNB - 1, b));
}

__global__ __launch_bounds__(256, 5)
void HistogramLayer_13048110645959_kernel(
    const float* __restrict__ inputs,   // [B, 16]
    const float* __restrict__ freq,     // [8, 16]
    const float* __restrict__ edges,    // [9, 16]
    float* __restrict__ out,            // [B]
    int B)
{
    __shared__ float s_prob[HD * HNB];        // [d][b]
    __shared__ float s_pair[(HD / 2) * 64];   // [pair][b0][b1], 2 KB

    const int tid = threadIdx.x;

    if (tid < HD * HNB) {
        const int d = tid >> 3;
        const int b = tid & 7;
        float s = 0.f;
        #pragma unroll
        for (int k = 0; k < HNB; ++k) s += freq[k * HD + d];
        s_prob[d * HNB + b] = freq[b * HD + d] / s;
    }
    __syncthreads();
    #pragma unroll
    for (int i = tid; i < (HD / 2) * 64; i += 256) {
        const int p  = i >> 6;
        const int b0 = (i >> 3) & 7;
        const int b1 = i & 7;
        s_pair[i] = s_prob[(2 * p) * HNB + b0] * s_prob[(2 * p + 1) * HNB + b1];
    }
    __syncthreads();

    // ~1/scale per feature in registers (uniform). e8 only needed on the rare
    // slow path -> reloaded from global there (uniform L1-hit LDG).
    float inv[HD];
    #pragma unroll
    for (int d = 0; d < HD; ++d)
        inv[d] = __fdividef(4.0f, edges[8 * HD + d]);

    const int stride = gridDim.x * blockDim.x;

    for (int row = blockIdx.x * blockDim.x + tid; row < B; row += stride) {
        const float4* in4 = reinterpret_cast<const float4*>(inputs + (size_t)row * HD);
        const float4 v0 = in4[0];
        const float4 v1 = in4[1];
        const float4 v2 = in4[2];
        const float4 v3 = in4[3];

        float x[HD];
        x[0]=v0.x;  x[1]=v0.y;  x[2]=v0.z;  x[3]=v0.w;
        x[4]=v1.x;  x[5]=v1.y;  x[6]=v1.z;  x[7]=v1.w;
        x[8]=v2.x;  x[9]=v2.y;  x[10]=v2.z; x[11]=v2.w;
        x[12]=v3.x; x[13]=v3.y; x[14]=v3.z; x[15]=v3.w;

        float m0 = 1.0f, m1 = 1.0f;
        int idx[HD / 2];
        #pragma unroll
        for (int p = 0; p < HD / 2; ++p) {
            const int b0 = fast_bin(x[2 * p],     inv[2 * p],     m0);
            const int b1 = fast_bin(x[2 * p + 1], inv[2 * p + 1], m1);
            idx[p] = (b0 << 3) + b1;
        }

        const unsigned am = __activemask();
        if (!__all_sync(am, fminf(m0, m1) > EPSQ)) {
            // Some lane is within EPS of a boundary: redo the whole warp-row
            // with the bit-exact rounded-edge comparison.
            #pragma unroll
            for (int p = 0; p < HD / 2; ++p) {
                const float e8a = edges[8 * HD + 2 * p];
                const float e8b = edges[8 * HD + 2 * p + 1];
                const int b0 = find_bin_slow(x[2 * p],     inv[2 * p],     e8a);
                const int b1 = find_bin_slow(x[2 * p + 1], inv[2 * p + 1], e8b);
                idx[p] = (b0 << 3) + b1;
            }
        }

        float prod0 = 1.0f, prod1 = 1.0f;
        #pragma unroll
        for (int p = 0; p < HD / 2; ++p) {
            const float pp = s_pair[(p << 6) + idx[p]];
            if (p & 1) prod1 *= pp; else prod0 *= pp;
        }
        out[row] = prod0 * prod1;
    }
}

extern "C" void kernel_launch(void* const* d_in, const int* in_sizes, int n_in,
                              void* d_out, int out_size)
{
    // Identify tensors by element count:
    //   inputs: B*16 (large), frequencies: 8*16=128, edges: 9*16=144.
    const float* inputs = nullptr;
    const float* freq   = nullptr;
    const float* edges  = nullptr;
    int B = 0;
    for (int i = 0; i < n_in; ++i) {
        if (in_sizes[i] == HNB * HD)            freq   = (const float*)d_in[i];
        else if (in_sizes[i] == (HNB + 1) * HD) edges  = (const float*)d_in[i];
        else { inputs = (const float*)d_in[i];  B = in_sizes[i] / HD; }
    }

    float* out = (float*)d_out;
    // 152 SMs * 5 CTAs/SM (reg-capped) * 2 scheduling waves.
    int blocks = 1520;
    const int max_needed = (B + 255) / 256;
    if (blocks > max_needed) blocks = max_needed;
    if (blocks < 1) blocks = 1;
    HistogramLayer_13048110645959_kernel<<<blocks, 256>>>(inputs, freq, edges, out, B);
}